// round 1
// baseline (speedup 1.0000x reference)
#include <cuda_runtime.h>
#include <math.h>
#include <math_constants.h>

// ---------------------------------------------------------------------------
// RecurrenceAttention (Transformer-XL style), fp32 baseline.
//
// Pipeline:
//  1. concat_h:      h = [mem ; x]  per batch                       (4096x1024)
//  2. fill_pos:      B2[bz][j][64:128] = pos_emb[j, hh*64:*]        (pos part)
//     zero_a2row:    A2[hh(beta=0)][1023][64:128] = 0               (rel-shift)
//  3. sgemm<0>:      q = x @ Wq^T, epilogue scatters q+u -> A2[:,:, 0:64]
//                    and shifted q+v -> A2[:,:,64:128]
//  4. sgemm<1>:      kv = h @ Wkv^T, epilogue scatters k -> B2[:,:,0:64],
//                    v -> V
//  5. sgemm<2>:      S[bz] = A2[bz] @ B2[bz]^T  (batched, K=128),
//                    epilogue: mask (j > i+1024 -> -1e30) + *0.125
//  6. colstats:      per column j: M[j]=max_i S, RZ[j]=1/sum_i exp(S-M)
//  7. out_gemm:      out[i,d] = sum_j exp(S[i,j]-M[j])*RZ[j] * V[j,d]
//  8. sgemm<3>:      y = out @ Wfc^T + x + bfc
//  9. ln_kernel:     LayerNorm rows -> d_out
// ---------------------------------------------------------------------------

#define B_      2
#define CUR_    1024
#define TOT_    2048
#define NH_     16
#define DH_     64
#define DM_     1024

// Scratch (static __device__, no allocations)
__device__ float g_h  [4096 * 1024];          // 16 MB
__device__ float g_A2 [32 * 1024 * 128];      // 16 MB  [bz][i][0:64]=q+u, [64:128]=shift(q+v)
__device__ float g_B2 [32 * 2048 * 128];      // 32 MB  [bz][j][0:64]=k,   [64:128]=pos
__device__ float g_V  [32 * 2048 * 64];       // 16 MB
__device__ float g_S  [32u * 1024u * 2048u];  // 256 MB
__device__ float g_M  [32 * 2048];
__device__ float g_RZ [32 * 2048];
__device__ float g_of [2048 * 1024];          // out (flat, row-major s x 1024)
__device__ float g_y  [2048 * 1024];

// ---------------------------------------------------------------------------
// concat h = [mem ; x] along seq, per batch. float4 granularity.
// ---------------------------------------------------------------------------
__global__ __launch_bounds__(256) void concat_h(const float* __restrict__ x,
                                                const float* __restrict__ mem) {
    size_t idx = (size_t)blockIdx.x * 256 + threadIdx.x;   // float4 index
    size_t r   = idx >> 8;                                 // row (0..4095)
    int    c4  = (int)(idx & 255);
    int beta = (int)(r >> 11);
    int s    = (int)(r & 2047);
    const float* src = (s < 1024)
        ? mem + ((size_t)(beta * 1024 + s)) * 1024
        : x   + ((size_t)(beta * 1024 + s - 1024)) * 1024;
    reinterpret_cast<float4*>(g_h)[idx] =
        reinterpret_cast<const float4*>(src)[c4];
}

// ---------------------------------------------------------------------------
// B2 pos half: B2[bz][j][64+d] = pos_emb[j*1024 + hh*64 + d]
// total 32*2048*16 float4 work items
// ---------------------------------------------------------------------------
__global__ __launch_bounds__(256) void fill_pos(const float* __restrict__ pos_emb) {
    int idx = blockIdx.x * 256 + threadIdx.x;   // 0 .. 1048575
    int d4 = idx & 15;
    int j  = (idx >> 4) & 2047;
    int bz = idx >> 15;
    int hh = bz & 15;
    float4 p = *reinterpret_cast<const float4*>(pos_emb + (size_t)j * 1024 + hh * 64 + d4 * 4);
    *reinterpret_cast<float4*>(g_B2 + (((size_t)bz * 2048 + j) * 128) + 64 + d4 * 4) = p;
}

// rel-shift: for beta=0 row 1023 of the q+v half is zero
__global__ __launch_bounds__(256) void zero_a2row() {
    int t = blockIdx.x * 256 + threadIdx.x;     // 0..1023
    int hh = t >> 6, d = t & 63;
    g_A2[(((size_t)hh) * 1024 + 1023) * 128 + 64 + d] = 0.0f;
}

// ---------------------------------------------------------------------------
// Generic NT SGEMM: C = A(MxK) * B(NxK)^T, row-major, lda=ldb=K.
// 128x128 block tile, BK=16, 8x8 per thread, 256 threads.
// MODE selects the fused epilogue (see pipeline above).
// ---------------------------------------------------------------------------
template <int MODE>
__global__ __launch_bounds__(256)
void sgemm_nt(const float* __restrict__ Ag, const float* __restrict__ Bg,
              int M, int N, int K,
              const float* __restrict__ aux0, const float* __restrict__ aux1,
              float* __restrict__ D0, float* __restrict__ D1) {
    __shared__ float As[16][132];
    __shared__ float Bs[16][132];

    const float* A = Ag;
    const float* B = Bg;
    if (MODE == 2) {
        int bz = blockIdx.z;
        A += (size_t)bz * M * K;
        B += (size_t)bz * N * K;
    }
    int rowBase = blockIdx.y * 128;
    int colBase = blockIdx.x * 128;
    int t  = threadIdx.x;
    int lr = t >> 2;          // 0..63  (tile row for loads)
    int lc = (t & 3) << 2;    // 0,4,8,12
    int ty = t >> 4;          // 0..15
    int tx = t & 15;          // 0..15

    float acc[8][8];
#pragma unroll
    for (int i = 0; i < 8; i++)
#pragma unroll
        for (int j = 0; j < 8; j++) acc[i][j] = 0.0f;

    for (int k0 = 0; k0 < K; k0 += 16) {
#pragma unroll
        for (int rr = 0; rr < 2; rr++) {
            int r = lr + rr * 64;
            float4 av = *reinterpret_cast<const float4*>(
                A + (size_t)(rowBase + r) * K + k0 + lc);
            As[lc + 0][r] = av.x; As[lc + 1][r] = av.y;
            As[lc + 2][r] = av.z; As[lc + 3][r] = av.w;
            float4 bv = *reinterpret_cast<const float4*>(
                B + (size_t)(colBase + r) * K + k0 + lc);
            Bs[lc + 0][r] = bv.x; Bs[lc + 1][r] = bv.y;
            Bs[lc + 2][r] = bv.z; Bs[lc + 3][r] = bv.w;
        }
        __syncthreads();
#pragma unroll
        for (int k = 0; k < 16; k++) {
            float4 a0 = *reinterpret_cast<const float4*>(&As[k][ty * 8]);
            float4 a1 = *reinterpret_cast<const float4*>(&As[k][ty * 8 + 4]);
            float4 b0 = *reinterpret_cast<const float4*>(&Bs[k][tx * 8]);
            float4 b1 = *reinterpret_cast<const float4*>(&Bs[k][tx * 8 + 4]);
            float a[8] = {a0.x, a0.y, a0.z, a0.w, a1.x, a1.y, a1.z, a1.w};
            float b[8] = {b0.x, b0.y, b0.z, b0.w, b1.x, b1.y, b1.z, b1.w};
#pragma unroll
            for (int i = 0; i < 8; i++)
#pragma unroll
                for (int j = 0; j < 8; j++)
                    acc[i][j] = fmaf(a[i], b[j], acc[i][j]);
        }
        __syncthreads();
    }

#pragma unroll
    for (int i = 0; i < 8; i++) {
        int gr = rowBase + ty * 8 + i;
#pragma unroll
        for (int j = 0; j < 8; j++) {
            int gc = colBase + tx * 8 + j;
            float val = acc[i][j];
            if (MODE == 0) {
                // q projection: aux0=u (1024), aux1=v (1024). D0 = A2.
                int betaB = gr >> 10, iq = gr & 1023;
                int hh = gc >> 6, d = gc & 63;
                size_t bz = (size_t)(betaB * 16 + hh);
                D0[(bz * 1024 + iq) * 128 + d] = val + aux0[gc];
                float pv = val + aux1[gc];
                if (betaB == 1) {
                    D0[(bz * 1024 + iq) * 128 + 64 + d] = pv;
                } else if (iq >= 1) {
                    // rel-shift: q row iq feeds shifted row iq-1 (beta=0)
                    D0[(bz * 1024 + (iq - 1)) * 128 + 64 + d] = pv;
                }
            } else if (MODE == 1) {
                // kv projection: D0 = B2 (k half), D1 = V.
                int betaB = gr >> 11, jj = gr & 2047;
                if (gc < 1024) {
                    int hh = gc >> 6, d = gc & 63;
                    D0[(((size_t)(betaB * 16 + hh)) * 2048 + jj) * 128 + d] = val;
                } else {
                    int c = gc - 1024;
                    int hh = c >> 6, d = c & 63;
                    D1[(((size_t)(betaB * 16 + hh)) * 2048 + jj) * 64 + d] = val;
                }
            } else if (MODE == 2) {
                // scores: mask j > i + PREV, scale by 1/sqrt(64)
                float s = (gc > gr + 1024) ? -1e30f : val * 0.125f;
                D0[((size_t)blockIdx.z * 1024 + gr) * 2048 + gc] = s;
            } else {
                // y = out@Wfc^T + x + bfc ; aux0 = x (flat), aux1 = bfc
                D0[(size_t)gr * 1024 + gc] =
                    val + aux0[(size_t)gr * 1024 + gc] + aux1[gc];
            }
        }
    }
}

// ---------------------------------------------------------------------------
// Column softmax stats over the QUERY axis i (softmax axis=1 in reference):
// per (bz, j): M = max_i S[i,j], RZ = 1/sum_i exp(S[i,j]-M). Online one-pass.
// ---------------------------------------------------------------------------
__global__ __launch_bounds__(256) void colstats() {
    int bz = blockIdx.y;
    int j  = blockIdx.x * 256 + threadIdx.x;
    const float* s = g_S + ((size_t)bz * 1024) * 2048 + j;
    float m = -CUDART_INF_F;
    float z = 0.0f;
#pragma unroll 4
    for (int i = 0; i < 1024; i++) {
        float v = s[(size_t)i * 2048];
        float nm = fmaxf(m, v);
        z = z * __expf(m - nm) + __expf(v - nm);
        m = nm;
    }
    g_M [bz * 2048 + j] = m;
    g_RZ[bz * 2048 + j] = 1.0f / z;
}

// ---------------------------------------------------------------------------
// out[i,d] = sum_j exp(S[i,j]-M[j])*RZ[j] * V[j,d]  per (bz).
// BM=128, BN=64, BK=16, 256 threads, 8x4 per thread. Writes flat out layout.
// ---------------------------------------------------------------------------
__global__ __launch_bounds__(256) void out_gemm() {
    __shared__ float As[16][132];
    __shared__ float Bs[16][64];

    int bz    = blockIdx.y;            // 0..31
    int mtile = blockIdx.x;            // 0..7
    const float* Sb = g_S + (size_t)bz * 1024 * 2048;
    const float* Vb = g_V + (size_t)bz * 2048 * 64;
    const float* Mc = g_M  + bz * 2048;
    const float* Rc = g_RZ + bz * 2048;

    int t  = threadIdx.x;
    int lr = t >> 2;            // 0..63
    int lc = (t & 3) << 2;      // 0,4,8,12
    int brow = t >> 4;          // 0..15
    int bcol = (t & 15) << 2;   // 0..60
    int ty = t >> 4;
    int tx = t & 15;
    int rowBase = mtile * 128;

    float acc[8][4];
#pragma unroll
    for (int i = 0; i < 8; i++)
#pragma unroll
        for (int j = 0; j < 4; j++) acc[i][j] = 0.0f;

    for (int k0 = 0; k0 < 2048; k0 += 16) {
        float4 mc = *reinterpret_cast<const float4*>(Mc + k0 + lc);
        float4 rc = *reinterpret_cast<const float4*>(Rc + k0 + lc);
#pragma unroll
        for (int rr = 0; rr < 2; rr++) {
            int r = lr + rr * 64;
            float4 sv = *reinterpret_cast<const float4*>(
                Sb + (size_t)(rowBase + r) * 2048 + k0 + lc);
            As[lc + 0][r] = __expf(sv.x - mc.x) * rc.x;
            As[lc + 1][r] = __expf(sv.y - mc.y) * rc.y;
            As[lc + 2][r] = __expf(sv.z - mc.z) * rc.z;
            As[lc + 3][r] = __expf(sv.w - mc.w) * rc.w;
        }
        *reinterpret_cast<float4*>(&Bs[brow][bcol]) =
            *reinterpret_cast<const float4*>(Vb + (size_t)(k0 + brow) * 64 + bcol);
        __syncthreads();
#pragma unroll
        for (int k = 0; k < 16; k++) {
            float4 a0 = *reinterpret_cast<const float4*>(&As[k][ty * 8]);
            float4 a1 = *reinterpret_cast<const float4*>(&As[k][ty * 8 + 4]);
            float4 bb = *reinterpret_cast<const float4*>(&Bs[k][tx * 4]);
            float a[8] = {a0.x, a0.y, a0.z, a0.w, a1.x, a1.y, a1.z, a1.w};
            float b[4] = {bb.x, bb.y, bb.z, bb.w};
#pragma unroll
            for (int i = 0; i < 8; i++)
#pragma unroll
                for (int j = 0; j < 4; j++)
                    acc[i][j] = fmaf(a[i], b[j], acc[i][j]);
        }
        __syncthreads();
    }

    int beta = bz >> 4, hh = bz & 15;
#pragma unroll
    for (int i = 0; i < 8; i++) {
        int gi = rowBase + ty * 8 + i;
#pragma unroll
        for (int j = 0; j < 4; j++) {
            g_of[((size_t)(beta * 1024 + gi)) * 1024 + hh * 64 + tx * 4 + j] = acc[i][j];
        }
    }
}

// ---------------------------------------------------------------------------
// LayerNorm over last dim (1024), one block per row.
// ---------------------------------------------------------------------------
__global__ __launch_bounds__(256) void ln_kernel(const float* __restrict__ gamma,
                                                 const float* __restrict__ beta,
                                                 float* __restrict__ out) {
    int row = blockIdx.x;
    const float4* yr = reinterpret_cast<const float4*>(g_y + (size_t)row * 1024);
    int t = threadIdx.x;
    float4 v = yr[t];
    float s  = v.x + v.y + v.z + v.w;
    float s2 = v.x * v.x + v.y * v.y + v.z * v.z + v.w * v.w;
#pragma unroll
    for (int off = 16; off; off >>= 1) {
        s  += __shfl_xor_sync(0xFFFFFFFFu, s,  off);
        s2 += __shfl_xor_sync(0xFFFFFFFFu, s2, off);
    }
    __shared__ float shs[8], shs2[8];
    int w = t >> 5, lane = t & 31;
    if (lane == 0) { shs[w] = s; shs2[w] = s2; }
    __syncthreads();
    float ts = 0.0f, ts2 = 0.0f;
#pragma unroll
    for (int i = 0; i < 8; i++) { ts += shs[i]; ts2 += shs2[i]; }
    float mu   = ts * (1.0f / 1024.0f);
    float var  = ts2 * (1.0f / 1024.0f) - mu * mu;
    float rstd = rsqrtf(var + 1e-5f);

    float4 g = reinterpret_cast<const float4*>(gamma)[t];
    float4 b = reinterpret_cast<const float4*>(beta)[t];
    float4 o;
    o.x = (v.x - mu) * rstd * g.x + b.x;
    o.y = (v.y - mu) * rstd * g.y + b.y;
    o.z = (v.z - mu) * rstd * g.z + b.z;
    o.w = (v.w - mu) * rstd * g.w + b.w;
    reinterpret_cast<float4*>(out + (size_t)row * 1024)[t] = o;
}

// ---------------------------------------------------------------------------
extern "C" void kernel_launch(void* const* d_in, const int* in_sizes, int n_in,
                              void* d_out, int out_size) {
    const float* x    = (const float*)d_in[0];
    const float* pos  = (const float*)d_in[1];
    const float* u    = (const float*)d_in[2];
    const float* v    = (const float*)d_in[3];
    const float* mem  = (const float*)d_in[4];
    // d_in[5] = tgt_mask (recomputed analytically)
    const float* Wq   = (const float*)d_in[6];
    const float* Wkv  = (const float*)d_in[7];
    const float* Wfc  = (const float*)d_in[8];
    const float* bfc  = (const float*)d_in[9];
    const float* gam  = (const float*)d_in[10];
    const float* bet  = (const float*)d_in[11];
    float* out = (float*)d_out;

    float *A2, *B2, *Vb, *h, *of, *y;
    cudaGetSymbolAddress((void**)&h,  g_h);
    cudaGetSymbolAddress((void**)&A2, g_A2);
    cudaGetSymbolAddress((void**)&B2, g_B2);
    cudaGetSymbolAddress((void**)&Vb, g_V);
    cudaGetSymbolAddress((void**)&of, g_of);
    cudaGetSymbolAddress((void**)&y,  g_y);

    concat_h  <<<4096, 256>>>(x, mem);
    fill_pos  <<<4096, 256>>>(pos);
    zero_a2row<<<4, 256>>>();

    // q projection -> A2 (with u/v add + rel-shift scatter)
    sgemm_nt<0><<<dim3(8, 16, 1), 256>>>(x, Wq, 2048, 1024, 1024, u, v, A2, nullptr);
    // kv projection -> B2 (k half) + V
    sgemm_nt<1><<<dim3(16, 32, 1), 256>>>(h, Wkv, 4096, 2048, 1024, nullptr, nullptr, B2, Vb);
    // scores (batched over 32 (beta,head)): S = A2 @ B2^T, mask + scale
    float* Sp; cudaGetSymbolAddress((void**)&Sp, g_S);
    sgemm_nt<2><<<dim3(16, 8, 32), 256>>>(A2, B2, 1024, 2048, 128, nullptr, nullptr, Sp, nullptr);
    // column (query-axis) softmax stats
    colstats<<<dim3(8, 32), 256>>>();
    // out = P @ V (exp transform fused into A load)
    out_gemm<<<dim3(8, 32), 256>>>();
    // y = out @ Wfc^T + x + bfc
    sgemm_nt<3><<<dim3(8, 16, 1), 256>>>(of, Wfc, 2048, 1024, 1024, x, bfc, y, nullptr);
    // LayerNorm -> output
    ln_kernel<<<2048, 256>>>(gam, bet, out);
}

// round 3
// speedup vs baseline: 2.1432x; 2.1432x over previous
#include <cuda_runtime.h>
#include <cstdint>
#include <math.h>
#include <math_constants.h>

// ===========================================================================
// RecurrenceAttention — mma.sync tf32 version (baseline PTX, works on the
// harness's compute_100 target; tcgen05 is unavailable there).
//
//  concat_h   : h = [mem ; x]
//  fill_pos   : B2[bz][j][64:128] = pos_emb ; zero_a2row (rel-shift row)
//  G0         : q = x@Wq^T        -> A2 (q+u | shifted q+v), fused scatter
//  G1         : kv = h@Wkv^T      -> B2 k-half, V transposed (Vt[d][j])
//  G2         : S = A2@B2^T (batched 32, K=128), mask+scale epilogue,
//               fully-masked tiles short-circuited
//  colstats   : per column j: M=max_i S, RZ=1/sum_i exp(S-M)  (poly exp)
//  G3         : out = (exp(S-M)*RZ) @ Vt^T  (transform fused into A load;
//               fully-masked K-chunks skipped)
//  G4         : y = out@Wfc^T + x + bfc
//  ln_kernel  : LayerNorm -> d_out
// ===========================================================================

// ---------------- scratch ----------------
__device__ float g_h  [4096 * 1024];
__device__ float g_A2 [32 * 1024 * 128];
__device__ float g_B2 [32 * 2048 * 128];
__device__ float g_V  [32 * 64 * 2048];        // TRANSPOSED: [bz][d][j]
__device__ float g_S  [32u * 1024u * 2048u];
__device__ float g_M  [32 * 2048];
__device__ float g_RZ [32 * 2048];
__device__ float g_of [2048 * 1024];
__device__ float g_y  [2048 * 1024];

// ---------------- helpers ----------------
__device__ __forceinline__ uint32_t f2tf32(float x) {
    uint32_t r;
    asm("cvt.rna.tf32.f32 %0, %1;" : "=r"(r) : "f"(x));
    return r;
}

__device__ __forceinline__ void mma8(float* c, const uint32_t* a, const uint32_t* b) {
    asm volatile(
        "mma.sync.aligned.m16n8k8.row.col.f32.tf32.tf32.f32 "
        "{%0,%1,%2,%3}, {%4,%5,%6,%7}, {%8,%9}, {%0,%1,%2,%3};"
        : "+f"(c[0]), "+f"(c[1]), "+f"(c[2]), "+f"(c[3])
        : "r"(a[0]), "r"(a[1]), "r"(a[2]), "r"(a[3]), "r"(b[0]), "r"(b[1]));
}

// fast exp on FMA pipe (cephes 2^f poly), exact enough for softmax
__device__ __forceinline__ float fexp(float x) {
    float y = fmaxf(x * 1.4426950408889634f, -126.0f);
    float fn = floorf(y);
    float f  = y - fn;
    float p  = 1.5403530e-4f;
    p = fmaf(p, f, 1.3333558e-3f);
    p = fmaf(p, f, 9.6181291e-3f);
    p = fmaf(p, f, 5.5504109e-2f);
    p = fmaf(p, f, 2.4022651e-1f);
    p = fmaf(p, f, 6.9314718e-1f);
    p = fmaf(p, f, 1.0f);
    return p * __int_as_float(((int)fn + 127) << 23);
}

// ---------------- small kernels ----------------
__global__ __launch_bounds__(256) void concat_h(const float* __restrict__ x,
                                                const float* __restrict__ mem) {
    size_t idx = (size_t)blockIdx.x * 256 + threadIdx.x;
    size_t r   = idx >> 8;
    int    c4  = (int)(idx & 255);
    int beta = (int)(r >> 11);
    int s    = (int)(r & 2047);
    const float* src = (s < 1024)
        ? mem + ((size_t)(beta * 1024 + s)) * 1024
        : x   + ((size_t)(beta * 1024 + s - 1024)) * 1024;
    reinterpret_cast<float4*>(g_h)[idx] =
        reinterpret_cast<const float4*>(src)[c4];
}

__global__ __launch_bounds__(256) void fill_pos(const float* __restrict__ pos_emb) {
    int idx = blockIdx.x * 256 + threadIdx.x;
    int d4 = idx & 15;
    int j  = (idx >> 4) & 2047;
    int bz = idx >> 15;
    int hh = bz & 15;
    float4 p = *reinterpret_cast<const float4*>(pos_emb + (size_t)j * 1024 + hh * 64 + d4 * 4);
    *reinterpret_cast<float4*>(g_B2 + (((size_t)bz * 2048 + j) * 128) + 64 + d4 * 4) = p;
}

__global__ __launch_bounds__(256) void zero_a2row() {
    int t = blockIdx.x * 256 + threadIdx.x;
    int hh = t >> 6, d = t & 63;
    g_A2[(((size_t)hh) * 1024 + 1023) * 128 + 64 + d] = 0.0f;
}

// ---------------------------------------------------------------------------
// tf32 mma.sync GEMM: D(M x N) = A(M x K) * B(N x K)^T, K-major inputs.
// BM=128, BN=128 or 64, BK=16, 256 threads (8 warps, 4x2 grid, 32 x BN/2 per
// warp). Double-buffered SMEM, pad-20 rows (conflict-free frag loads).
// MODE: 0=qproj  1=kvproj  2=scores  3=P@V  4=fc
// ---------------------------------------------------------------------------
template <int MODE, int BN>
__global__ __launch_bounds__(256)
void gemm_mma(const float* __restrict__ Ag, const float* __restrict__ Bg, int K,
              size_t batchA, size_t batchB,
              const float* __restrict__ aux0, const float* __restrict__ aux1,
              float* __restrict__ D0, float* __restrict__ D1) {
    constexpr int LDS_ = 20;               // 16 data + 4 pad floats per row
    constexpr int WN   = BN / 2;           // warp tile N
    constexpr int NT   = WN / 8;           // n-tiles per warp
    constexpr int NB4  = BN / 64;          // B float4 loads per thread
    __shared__ __align__(16) float sA[2][128 * LDS_];
    __shared__ __align__(16) float sB[2][BN * LDS_];

    const int t    = threadIdx.x;
    const int wid  = t >> 5;
    const int lane = t & 31;
    const int wm   = wid >> 1;             // 0..3
    const int wn   = wid & 1;              // 0..1
    const int group = lane >> 2;           // 0..7
    const int tid4  = lane & 3;            // 0..3
    const int rowBase = blockIdx.y * 128;
    const int colBase = blockIdx.x * BN;

    const float* A = Ag + (size_t)blockIdx.z * batchA;
    const float* B = Bg + (size_t)blockIdx.z * batchB;
    const float* Mc = (MODE == 3) ? aux0 + (size_t)blockIdx.z * 2048 : aux0;
    const float* Rc = (MODE == 3) ? aux1 + (size_t)blockIdx.z * 2048 : aux1;

    // fully-masked score tiles: fill -1e30, exit
    if (MODE == 2 && colBase > rowBase + 1151) {
        size_t base = ((size_t)blockIdx.z * 1024 + rowBase) * 2048 + colBase;
        float4 mfill = make_float4(-1e30f, -1e30f, -1e30f, -1e30f);
#pragma unroll
        for (int i = 0; i < 16; i++) {
            int e = i * 256 + t;
            int row = e >> 5, c4 = e & 31;
            *reinterpret_cast<float4*>(D0 + base + (size_t)row * 2048 + c4 * 4) = mfill;
        }
        return;
    }

    int nch = K >> 4;
    if (MODE == 3) {
        int lim = ((rowBase + 1151) >> 4) + 1;   // skip fully-masked K-chunks
        if (lim < nch) nch = lim;
    }

    float acc[2][NT][4];
#pragma unroll
    for (int mt = 0; mt < 2; mt++)
#pragma unroll
        for (int nt = 0; nt < NT; nt++)
#pragma unroll
            for (int e = 0; e < 4; e++) acc[mt][nt][e] = 0.0f;

    float4 ra[2], rb[NB4];

    // ---- chunk loader (global -> regs), with MODE3 transform ----
    auto load_regs = [&](int ch) {
        const int k0 = ch << 4;
#pragma unroll
        for (int i = 0; i < 2; i++) {
            int e = i * 256 + t;
            int row = e >> 2, c4 = e & 3;
            float4 v = *reinterpret_cast<const float4*>(
                A + (size_t)(rowBase + row) * K + k0 + c4 * 4);
            if (MODE == 3) {
                int kg = k0 + c4 * 4;
                float4 mm = *reinterpret_cast<const float4*>(Mc + kg);
                float4 rz = *reinterpret_cast<const float4*>(Rc + kg);
                v.x = fexp(v.x - mm.x) * rz.x;
                v.y = fexp(v.y - mm.y) * rz.y;
                v.z = fexp(v.z - mm.z) * rz.z;
                v.w = fexp(v.w - mm.w) * rz.w;
            }
            ra[i] = v;
        }
#pragma unroll
        for (int i = 0; i < NB4; i++) {
            int e = i * 256 + t;
            int row = e >> 2, c4 = e & 3;
            rb[i] = *reinterpret_cast<const float4*>(
                B + (size_t)(colBase + row) * K + k0 + c4 * 4);
        }
    };

    auto sts_regs = [&](int buf) {
#pragma unroll
        for (int i = 0; i < 2; i++) {
            int e = i * 256 + t;
            int row = e >> 2, c4 = e & 3;
            float* p = &sA[buf][row * LDS_ + c4 * 4];
            p[0] = __uint_as_float(f2tf32(ra[i].x));
            p[1] = __uint_as_float(f2tf32(ra[i].y));
            p[2] = __uint_as_float(f2tf32(ra[i].z));
            p[3] = __uint_as_float(f2tf32(ra[i].w));
        }
#pragma unroll
        for (int i = 0; i < NB4; i++) {
            int e = i * 256 + t;
            int row = e >> 2, c4 = e & 3;
            float* p = &sB[buf][row * LDS_ + c4 * 4];
            p[0] = __uint_as_float(f2tf32(rb[i].x));
            p[1] = __uint_as_float(f2tf32(rb[i].y));
            p[2] = __uint_as_float(f2tf32(rb[i].z));
            p[3] = __uint_as_float(f2tf32(rb[i].w));
        }
    };

    load_regs(0);
    sts_regs(0);
    __syncthreads();

    int buf = 0;
    for (int ch = 0; ch < nch; ch++) {
        if (ch + 1 < nch) load_regs(ch + 1);

        // ---- compute on sA[buf], sB[buf] ----
#pragma unroll
        for (int ks = 0; ks < 2; ks++) {
            const int kk = ks * 8;
            uint32_t a[2][4];
#pragma unroll
            for (int mt = 0; mt < 2; mt++) {
                int r = wm * 32 + mt * 16;
                a[mt][0] = __float_as_uint(sA[buf][(r + group)     * LDS_ + kk + tid4]);
                a[mt][1] = __float_as_uint(sA[buf][(r + group + 8) * LDS_ + kk + tid4]);
                a[mt][2] = __float_as_uint(sA[buf][(r + group)     * LDS_ + kk + tid4 + 4]);
                a[mt][3] = __float_as_uint(sA[buf][(r + group + 8) * LDS_ + kk + tid4 + 4]);
            }
            uint32_t b[NT][2];
#pragma unroll
            for (int nt = 0; nt < NT; nt++) {
                int n = wn * WN + nt * 8 + group;
                b[nt][0] = __float_as_uint(sB[buf][n * LDS_ + kk + tid4]);
                b[nt][1] = __float_as_uint(sB[buf][n * LDS_ + kk + tid4 + 4]);
            }
#pragma unroll
            for (int mt = 0; mt < 2; mt++)
#pragma unroll
                for (int nt = 0; nt < NT; nt++)
                    mma8(acc[mt][nt], a[mt], b[nt]);
        }

        if (ch + 1 < nch) {
            __syncthreads();
            sts_regs(buf ^ 1);
            buf ^= 1;
            __syncthreads();
        }
    }

    // ---- epilogue: each thread owns pairs (gr, gc..gc+1) ----
    auto emit = [&](int gr, int gc, float v0, float v1) {
        if (MODE == 0) {
            float2 u2 = *reinterpret_cast<const float2*>(aux0 + gc);
            float2 w2 = *reinterpret_cast<const float2*>(aux1 + gc);
            int betaB = gr >> 10, iq = gr & 1023;
            int hh = gc >> 6, d = gc & 63;
            size_t base = ((size_t)(betaB * 16 + hh) * 1024 + iq) * 128 + d;
            float2 q = make_float2(v0 + u2.x, v1 + u2.y);
            float2 pv = make_float2(v0 + w2.x, v1 + w2.y);
            *reinterpret_cast<float2*>(D0 + base) = q;
            if (betaB == 1)
                *reinterpret_cast<float2*>(D0 + base + 64) = pv;
            else if (iq >= 1)
                *reinterpret_cast<float2*>(D0 + base - 64) = pv;  // (iq-1)*128 + 64 + d
        } else if (MODE == 1) {
            int betaB = gr >> 11, jj = gr & 2047;
            if (gc < 1024) {
                int hh = gc >> 6, d = gc & 63;
                *reinterpret_cast<float2*>(
                    D0 + ((size_t)(betaB * 16 + hh) * 2048 + jj) * 128 + d) =
                    make_float2(v0, v1);
            } else {
                int c = gc - 1024;
                int hh = c >> 6, d = c & 63;
                size_t base = ((size_t)(betaB * 16 + hh) * 64 + d) * 2048 + jj;
                D1[base]        = v0;
                D1[base + 2048] = v1;
            }
        } else if (MODE == 2) {
            size_t rowb = ((size_t)blockIdx.z * 1024 + gr) * 2048;
            float s0 = (gc + 0 > gr + 1024) ? -1e30f : v0 * 0.125f;
            float s1 = (gc + 1 > gr + 1024) ? -1e30f : v1 * 0.125f;
            *reinterpret_cast<float2*>(D0 + rowb + gc) = make_float2(s0, s1);
        } else if (MODE == 3) {
            int bz = blockIdx.z, beta = bz >> 4, hh = bz & 15;
            *reinterpret_cast<float2*>(
                D0 + ((size_t)(beta * 1024 + gr)) * 1024 + hh * 64 + gc) =
                make_float2(v0, v1);
        } else {
            float2 xv = *reinterpret_cast<const float2*>(aux0 + (size_t)gr * 1024 + gc);
            float2 bv = *reinterpret_cast<const float2*>(aux1 + gc);
            *reinterpret_cast<float2*>(D0 + (size_t)gr * 1024 + gc) =
                make_float2(v0 + xv.x + bv.x, v1 + xv.y + bv.y);
        }
    };

#pragma unroll
    for (int mt = 0; mt < 2; mt++) {
#pragma unroll
        for (int nt = 0; nt < NT; nt++) {
            int gr0 = rowBase + wm * 32 + mt * 16 + group;
            int gc  = colBase + wn * WN + nt * 8 + tid4 * 2;
            emit(gr0,     gc, acc[mt][nt][0], acc[mt][nt][1]);
            emit(gr0 + 8, gc, acc[mt][nt][2], acc[mt][nt][3]);
        }
    }
}

// ---------------------------------------------------------------------------
// Column softmax stats (softmax over query axis i): online max + exp-sum.
// ---------------------------------------------------------------------------
__global__ __launch_bounds__(256) void colstats() {
    int bz = blockIdx.y;
    int j  = blockIdx.x * 256 + threadIdx.x;
    const float* s = g_S + ((size_t)bz * 1024) * 2048 + j;
    float m = -CUDART_INF_F;
    float z = 0.0f;
#pragma unroll 4
    for (int i = 0; i < 1024; i++) {
        float v = s[(size_t)i * 2048];
        float nm = fmaxf(m, v);
        z = z * fexp(m - nm) + fexp(v - nm);
        m = nm;
    }
    g_M [bz * 2048 + j] = m;
    g_RZ[bz * 2048 + j] = 1.0f / z;
}

// ---------------------------------------------------------------------------
__global__ __launch_bounds__(256) void ln_kernel(const float* __restrict__ gamma,
                                                 const float* __restrict__ beta,
                                                 float* __restrict__ out) {
    int row = blockIdx.x;
    const float4* yr = reinterpret_cast<const float4*>(g_y + (size_t)row * 1024);
    int t = threadIdx.x;
    float4 v = yr[t];
    float s  = v.x + v.y + v.z + v.w;
    float s2 = v.x * v.x + v.y * v.y + v.z * v.z + v.w * v.w;
#pragma unroll
    for (int off = 16; off; off >>= 1) {
        s  += __shfl_xor_sync(0xFFFFFFFFu, s,  off);
        s2 += __shfl_xor_sync(0xFFFFFFFFu, s2, off);
    }
    __shared__ float shs[8], shs2[8];
    int w = t >> 5, lane = t & 31;
    if (lane == 0) { shs[w] = s; shs2[w] = s2; }
    __syncthreads();
    float ts = 0.0f, ts2 = 0.0f;
#pragma unroll
    for (int i = 0; i < 8; i++) { ts += shs[i]; ts2 += shs2[i]; }
    float mu   = ts * (1.0f / 1024.0f);
    float var  = ts2 * (1.0f / 1024.0f) - mu * mu;
    float rstd = rsqrtf(var + 1e-5f);

    float4 g = reinterpret_cast<const float4*>(gamma)[t];
    float4 b = reinterpret_cast<const float4*>(beta)[t];
    float4 o;
    o.x = (v.x - mu) * rstd * g.x + b.x;
    o.y = (v.y - mu) * rstd * g.y + b.y;
    o.z = (v.z - mu) * rstd * g.z + b.z;
    o.w = (v.w - mu) * rstd * g.w + b.w;
    reinterpret_cast<float4*>(out + (size_t)row * 1024)[t] = o;
}

// ---------------------------------------------------------------------------
extern "C" void kernel_launch(void* const* d_in, const int* in_sizes, int n_in,
                              void* d_out, int out_size) {
    const float* x    = (const float*)d_in[0];
    const float* pos  = (const float*)d_in[1];
    const float* u    = (const float*)d_in[2];
    const float* v    = (const float*)d_in[3];
    const float* mem  = (const float*)d_in[4];
    const float* Wq   = (const float*)d_in[6];
    const float* Wkv  = (const float*)d_in[7];
    const float* Wfc  = (const float*)d_in[8];
    const float* bfc  = (const float*)d_in[9];
    const float* gam  = (const float*)d_in[10];
    const float* bet  = (const float*)d_in[11];
    float* out = (float*)d_out;

    float *A2, *B2, *Vt, *h, *of, *y, *Sp, *Mp, *Rp;
    cudaGetSymbolAddress((void**)&h,  g_h);
    cudaGetSymbolAddress((void**)&A2, g_A2);
    cudaGetSymbolAddress((void**)&B2, g_B2);
    cudaGetSymbolAddress((void**)&Vt, g_V);
    cudaGetSymbolAddress((void**)&of, g_of);
    cudaGetSymbolAddress((void**)&y,  g_y);
    cudaGetSymbolAddress((void**)&Sp, g_S);
    cudaGetSymbolAddress((void**)&Mp, g_M);
    cudaGetSymbolAddress((void**)&Rp, g_RZ);

    concat_h  <<<4096, 256>>>(x, mem);
    fill_pos  <<<4096, 256>>>(pos);
    zero_a2row<<<4, 256>>>();

    // G0: q = x@Wq^T -> A2 (q+u | shifted q+v)
    gemm_mma<0, 128><<<dim3(8, 16, 1), 256>>>(x, Wq, 1024, 0, 0, u, v, A2, nullptr);
    // G1: kv = h@Wkv^T -> B2 k-half + Vt
    gemm_mma<1, 128><<<dim3(16, 32, 1), 256>>>(h, Wkv, 1024, 0, 0, nullptr, nullptr, B2, Vt);
    // G2: S = A2@B2^T batched over 32, K=128, mask+scale
    gemm_mma<2, 128><<<dim3(16, 8, 32), 256>>>(A2, B2, 128,
        (size_t)1024 * 128, (size_t)2048 * 128, nullptr, nullptr, Sp, nullptr);
    // softmax stats over query axis
    colstats<<<dim3(8, 32), 256>>>();
    // G3: out = (exp(S - M) * RZ) @ Vt^T
    gemm_mma<3, 64><<<dim3(1, 8, 32), 256>>>(Sp, Vt, 2048,
        (size_t)1024 * 2048, (size_t)64 * 2048, Mp, Rp, of, nullptr);
    // G4: y = out@Wfc^T + x + bfc
    gemm_mma<4, 128><<<dim3(8, 16, 1), 256>>>(of, Wfc, 1024, 0, 0, x, bfc, y, nullptr);
    // LayerNorm
    ln_kernel<<<2048, 256>>>(gam, bet, out);
}

// round 4
// speedup vs baseline: 2.4724x; 1.1536x over previous
#include <cuda_runtime.h>
#include <cuda_bf16.h>
#include <cstdint>
#include <math.h>
#include <math_constants.h>

// ===========================================================================
// RecurrenceAttention — bf16 mma.sync (m16n8k16) + ldmatrix version.
//
//  concat_h   : h = [mem ; x]                    (-> bf16)
//  fill_pos   : B2 pos half ; zero_a2row
//  G0         : q = x@Wq^T   -> A2 bf16 (q+u | shifted q+v)
//  G1         : kv = h@Wkv^T -> B2 bf16 k-half + Vt bf16 (transposed [d][j])
//  G2         : S = A2@B2^T  (batched 32, K=128), mask+scale -> S bf16;
//               fully-masked tiles short-circuited
//  colstats   : per col j: M=max_i S, RZ=1/sum_i exp(S-M)  (valid-i only)
//  G3         : out = (exp(S-M)*RZ) @ Vt^T -> of bf16 (transform in loader,
//               masked K-chunks skipped)
//  G4         : y = of@Wfc^T + x + bfc  (fp32 out)
//  ln_kernel  : LayerNorm -> d_out
// ===========================================================================

// ---------------- scratch ----------------
__device__ __nv_bfloat16 g_h  [4096 * 1024];
__device__ __nv_bfloat16 g_A2 [32 * 1024 * 128];
__device__ __nv_bfloat16 g_B2 [32 * 2048 * 128];
__device__ __nv_bfloat16 g_V  [32 * 64 * 2048];       // [bz][d][j]
__device__ __nv_bfloat16 g_S  [32u * 1024u * 2048u];  // 128 MB
__device__ float g_M  [32 * 2048];
__device__ float g_RZ [32 * 2048];
__device__ __nv_bfloat16 g_of [2048 * 1024];
__device__ float g_y  [2048 * 1024];

// ---------------- helpers ----------------
__device__ __forceinline__ uint32_t smem_u32(const void* p) {
    uint32_t a;
    asm("{ .reg .u64 t; cvta.to.shared.u64 t, %1; cvt.u32.u64 %0, t; }"
        : "=r"(a) : "l"(p));
    return a;
}
__device__ __forceinline__ uint32_t pack_bf2(float a, float b) {
    __nv_bfloat162 h = __float22bfloat162_rn(make_float2(a, b));
    return *reinterpret_cast<uint32_t*>(&h);
}
__device__ __forceinline__ void ldsm4(uint32_t* r, uint32_t addr) {
    asm volatile("ldmatrix.sync.aligned.m8n8.x4.shared.b16 {%0,%1,%2,%3}, [%4];"
                 : "=r"(r[0]), "=r"(r[1]), "=r"(r[2]), "=r"(r[3]) : "r"(addr));
}
__device__ __forceinline__ void mma16(float* c, const uint32_t* a,
                                      uint32_t b0, uint32_t b1) {
    asm volatile(
        "mma.sync.aligned.m16n8k16.row.col.f32.bf16.bf16.f32 "
        "{%0,%1,%2,%3}, {%4,%5,%6,%7}, {%8,%9}, {%0,%1,%2,%3};"
        : "+f"(c[0]), "+f"(c[1]), "+f"(c[2]), "+f"(c[3])
        : "r"(a[0]), "r"(a[1]), "r"(a[2]), "r"(a[3]), "r"(b0), "r"(b1));
}

// fast exp on FMA pipe (cephes-style 2^f poly)
__device__ __forceinline__ float fexp(float x) {
    float y = fmaxf(x * 1.4426950408889634f, -126.0f);
    float fn = floorf(y);
    float f  = y - fn;
    float p  = 1.5403530e-4f;
    p = fmaf(p, f, 1.3333558e-3f);
    p = fmaf(p, f, 9.6181291e-3f);
    p = fmaf(p, f, 5.5504109e-2f);
    p = fmaf(p, f, 2.4022651e-1f);
    p = fmaf(p, f, 6.9314718e-1f);
    p = fmaf(p, f, 1.0f);
    return p * __int_as_float(((int)fn + 127) << 23);
}

// ---------------- small kernels ----------------
__global__ __launch_bounds__(256) void concat_h(const float* __restrict__ x,
                                                const float* __restrict__ mem) {
    size_t idx = (size_t)blockIdx.x * 256 + threadIdx.x;   // group of 4 floats
    size_t r   = idx >> 8;
    int    c4  = (int)(idx & 255);
    int beta = (int)(r >> 11);
    int s    = (int)(r & 2047);
    const float* src = (s < 1024)
        ? mem + ((size_t)(beta * 1024 + s)) * 1024
        : x   + ((size_t)(beta * 1024 + s - 1024)) * 1024;
    float4 v = reinterpret_cast<const float4*>(src)[c4];
    uint2 o;
    o.x = pack_bf2(v.x, v.y);
    o.y = pack_bf2(v.z, v.w);
    *reinterpret_cast<uint2*>(g_h + idx * 4) = o;
}

__global__ __launch_bounds__(256) void fill_pos(const float* __restrict__ pos_emb) {
    int idx = blockIdx.x * 256 + threadIdx.x;
    int d4 = idx & 15;
    int j  = (idx >> 4) & 2047;
    int bz = idx >> 15;
    int hh = bz & 15;
    float4 p = *reinterpret_cast<const float4*>(pos_emb + (size_t)j * 1024 + hh * 64 + d4 * 4);
    uint2 o;
    o.x = pack_bf2(p.x, p.y);
    o.y = pack_bf2(p.z, p.w);
    *reinterpret_cast<uint2*>(g_B2 + (((size_t)bz * 2048 + j) * 128) + 64 + d4 * 4) = o;
}

__global__ __launch_bounds__(256) void zero_a2row() {
    int t = blockIdx.x * 256 + threadIdx.x;     // 0..1023
    int hh = t >> 6, d = t & 63;
    g_A2[(((size_t)hh) * 1024 + 1023) * 128 + 64 + d] = __float2bfloat16(0.0f);
}

// ---------------------------------------------------------------------------
// bf16 GEMM: D(M x N) = A(M x K) * B(N x K)^T, K-major inputs.
// BM=128, BN=128/64, BK=32 (bf16). 256 threads, 8 warps 4x2.
// SMEM rows padded to 80B (conflict-free ldmatrix). Double-buffered.
// MODE: 0=qproj  1=kvproj  2=scores  3=P@V  4=fc
// ---------------------------------------------------------------------------
template <int MODE, int BN>
__global__ __launch_bounds__(256, 2)
void gemm_bf16(const void* __restrict__ Agv, const void* __restrict__ Bgv, int K,
               size_t batchA, size_t batchB,
               const float* __restrict__ aux0, const float* __restrict__ aux1,
               void* __restrict__ D0v, void* __restrict__ D1v) {
    constexpr bool ABF  = (MODE != 0);             // A already bf16?
    constexpr bool BBF  = (MODE == 2 || MODE == 3);
    constexpr int  WN    = BN / 2;
    constexpr int  NT    = WN / 8;
    constexpr int  NG    = WN / 16;                // ldmatrix n16 groups
    constexpr int  BPASS = BN / 64;                // B chunk passes

    __shared__ __align__(16) uint8_t sA[2][128 * 80];
    __shared__ __align__(16) uint8_t sB[2][BN * 80];

    const int t    = threadIdx.x;
    const int wid  = t >> 5;
    const int lane = t & 31;
    const int wm   = wid >> 1;
    const int wn   = wid & 1;
    const int group = lane >> 2;
    const int tid4  = lane & 3;
    const int rowBase = blockIdx.y * 128;
    const int colBase = blockIdx.x * BN;

    // fully-masked score tiles: fill -1e30 bf16, exit
    if (MODE == 2 && colBase > rowBase + 1151) {
        __nv_bfloat16* Sp = (__nv_bfloat16*)D0v;
        size_t base = ((size_t)blockIdx.z * 1024 + rowBase) * 2048 + colBase;
        uint32_t mv = pack_bf2(-1e30f, -1e30f);
        uint4 fill = make_uint4(mv, mv, mv, mv);
#pragma unroll
        for (int i = 0; i < 8; i++) {
            int e = i * 256 + t;
            int row = e >> 4, c8 = e & 15;
            *reinterpret_cast<uint4*>(Sp + base + (size_t)row * 2048 + c8 * 8) = fill;
        }
        return;
    }

    const float* Af = ABF ? nullptr : (const float*)Agv + (size_t)blockIdx.z * batchA;
    const __nv_bfloat16* Ab = ABF ? (const __nv_bfloat16*)Agv + (size_t)blockIdx.z * batchA : nullptr;
    const float* Bf = BBF ? nullptr : (const float*)Bgv + (size_t)blockIdx.z * batchB;
    const __nv_bfloat16* Bb = BBF ? (const __nv_bfloat16*)Bgv + (size_t)blockIdx.z * batchB : nullptr;
    const float* Mc = (MODE == 3) ? aux0 + (size_t)blockIdx.z * 2048 : aux0;
    const float* Rc = (MODE == 3) ? aux1 + (size_t)blockIdx.z * 2048 : aux1;

    int nch = K >> 5;
    if (MODE == 3) {
        int lim = ((rowBase + 1151) >> 5) + 1;
        if (lim < nch) nch = lim;
    }

    float acc[2][NT][4];
#pragma unroll
    for (int mt = 0; mt < 2; mt++)
#pragma unroll
        for (int nt = 0; nt < NT; nt++)
#pragma unroll
            for (int e = 0; e < 4; e++) acc[mt][nt][e] = 0.0f;

    uint4 ra[2], rb[BPASS];

    auto load_regs = [&](int ch) {
        const int kg0 = ch << 5;
#pragma unroll
        for (int p = 0; p < 2; p++) {
            int idx = p * 256 + t;
            int c = idx >> 7, r = idx & 127;
            int kg = kg0 + c * 8;
            uint4 o;
            if (!ABF) {
                const float* src = Af + (size_t)(rowBase + r) * K + kg;
                float4 f0 = *reinterpret_cast<const float4*>(src);
                float4 f1 = *reinterpret_cast<const float4*>(src + 4);
                o.x = pack_bf2(f0.x, f0.y); o.y = pack_bf2(f0.z, f0.w);
                o.z = pack_bf2(f1.x, f1.y); o.w = pack_bf2(f1.z, f1.w);
            } else {
                o = *reinterpret_cast<const uint4*>(Ab + (size_t)(rowBase + r) * K + kg);
                if (MODE == 3) {
                    float4 m0 = *reinterpret_cast<const float4*>(Mc + kg);
                    float4 m1 = *reinterpret_cast<const float4*>(Mc + kg + 4);
                    float4 z0 = *reinterpret_cast<const float4*>(Rc + kg);
                    float4 z1 = *reinterpret_cast<const float4*>(Rc + kg + 4);
                    __nv_bfloat162* hp = reinterpret_cast<__nv_bfloat162*>(&o);
                    float2 p0 = __bfloat1622float2(hp[0]);
                    float2 p1 = __bfloat1622float2(hp[1]);
                    float2 p2 = __bfloat1622float2(hp[2]);
                    float2 p3 = __bfloat1622float2(hp[3]);
                    o.x = pack_bf2(fexp(p0.x - m0.x) * z0.x, fexp(p0.y - m0.y) * z0.y);
                    o.y = pack_bf2(fexp(p1.x - m0.z) * z0.z, fexp(p1.y - m0.w) * z0.w);
                    o.z = pack_bf2(fexp(p2.x - m1.x) * z1.x, fexp(p2.y - m1.y) * z1.y);
                    o.w = pack_bf2(fexp(p3.x - m1.z) * z1.z, fexp(p3.y - m1.w) * z1.w);
                }
            }
            ra[p] = o;
        }
#pragma unroll
        for (int p = 0; p < BPASS; p++) {
            int idx = p * 256 + t;
            int c = idx / BN, r = idx % BN;
            int kg = kg0 + c * 8;
            uint4 o;
            if (!BBF) {
                const float* src = Bf + (size_t)(colBase + r) * K + kg;
                float4 f0 = *reinterpret_cast<const float4*>(src);
                float4 f1 = *reinterpret_cast<const float4*>(src + 4);
                o.x = pack_bf2(f0.x, f0.y); o.y = pack_bf2(f0.z, f0.w);
                o.z = pack_bf2(f1.x, f1.y); o.w = pack_bf2(f1.z, f1.w);
            } else {
                o = *reinterpret_cast<const uint4*>(Bb + (size_t)(colBase + r) * K + kg);
            }
            rb[p] = o;
        }
    };

    auto sts_regs = [&](int buf) {
#pragma unroll
        for (int p = 0; p < 2; p++) {
            int idx = p * 256 + t;
            int c = idx >> 7, r = idx & 127;
            *reinterpret_cast<uint4*>(&sA[buf][r * 80 + c * 16]) = ra[p];
        }
#pragma unroll
        for (int p = 0; p < BPASS; p++) {
            int idx = p * 256 + t;
            int c = idx / BN, r = idx % BN;
            *reinterpret_cast<uint4*>(&sB[buf][r * 80 + c * 16]) = rb[p];
        }
    };

    load_regs(0);
    sts_regs(0);
    __syncthreads();

    const int lrow = (lane & 15) * 80;          // ldmatrix per-lane row offset
    const int kh   = ((lane >> 4) & 1) * 16;    // k-half select

    int buf = 0;
    for (int ch = 0; ch < nch; ch++) {
        if (ch + 1 < nch) load_regs(ch + 1);

        uint32_t aBase = smem_u32(&sA[buf][0]);
        uint32_t bBase = smem_u32(&sB[buf][0]);
#pragma unroll
        for (int ks = 0; ks < 2; ks++) {
            const int kb = ks * 32 + kh;
            uint32_t a[2][4];
#pragma unroll
            for (int mt = 0; mt < 2; mt++)
                ldsm4(a[mt], aBase + (wm * 32 + mt * 16) * 80 + lrow + kb);
            uint32_t bfr[NG][4];
#pragma unroll
            for (int g = 0; g < NG; g++)
                ldsm4(bfr[g], bBase + (wn * WN + g * 16) * 80 + lrow + kb);
#pragma unroll
            for (int mt = 0; mt < 2; mt++)
#pragma unroll
                for (int g = 0; g < NG; g++) {
                    mma16(acc[mt][2 * g],     a[mt], bfr[g][0], bfr[g][2]);
                    mma16(acc[mt][2 * g + 1], a[mt], bfr[g][1], bfr[g][3]);
                }
        }

        if (ch + 1 < nch) {
            __syncthreads();
            sts_regs(buf ^ 1);
            buf ^= 1;
            __syncthreads();
        }
    }

    // ---- epilogue ----
    auto emit = [&](int gr, int gc, float v0, float v1) {
        if (MODE == 0) {
            __nv_bfloat16* A2p = (__nv_bfloat16*)D0v;
            float2 u2 = *reinterpret_cast<const float2*>(aux0 + gc);
            float2 w2 = *reinterpret_cast<const float2*>(aux1 + gc);
            int betaB = gr >> 10, iq = gr & 1023;
            int hh = gc >> 6, d = gc & 63;
            size_t base = ((size_t)(betaB * 16 + hh) * 1024 + iq) * 128 + d;
            uint32_t q  = pack_bf2(v0 + u2.x, v1 + u2.y);
            uint32_t pv = pack_bf2(v0 + w2.x, v1 + w2.y);
            *reinterpret_cast<uint32_t*>(A2p + base) = q;
            if (betaB == 1)
                *reinterpret_cast<uint32_t*>(A2p + base + 64) = pv;
            else if (iq >= 1)
                *reinterpret_cast<uint32_t*>(A2p + base - 64) = pv;
        } else if (MODE == 1) {
            int betaB = gr >> 11, jj = gr & 2047;
            if (gc < 1024) {
                __nv_bfloat16* B2p = (__nv_bfloat16*)D0v;
                int hh = gc >> 6, d = gc & 63;
                *reinterpret_cast<uint32_t*>(
                    B2p + ((size_t)(betaB * 16 + hh) * 2048 + jj) * 128 + d) =
                    pack_bf2(v0, v1);
            } else {
                __nv_bfloat16* Vp = (__nv_bfloat16*)D1v;
                int c = gc - 1024;
                int hh = c >> 6, d = c & 63;
                size_t base = ((size_t)(betaB * 16 + hh) * 64 + d) * 2048 + jj;
                Vp[base]        = __float2bfloat16(v0);
                Vp[base + 2048] = __float2bfloat16(v1);
            }
        } else if (MODE == 2) {
            __nv_bfloat16* Sp = (__nv_bfloat16*)D0v;
            size_t rowb = ((size_t)blockIdx.z * 1024 + gr) * 2048;
            float s0 = (gc + 0 > gr + 1024) ? -1e30f : v0 * 0.125f;
            float s1 = (gc + 1 > gr + 1024) ? -1e30f : v1 * 0.125f;
            *reinterpret_cast<uint32_t*>(Sp + rowb + gc) = pack_bf2(s0, s1);
        } else if (MODE == 3) {
            __nv_bfloat16* Op = (__nv_bfloat16*)D0v;
            int bz = blockIdx.z, beta = bz >> 4, hh = bz & 15;
            *reinterpret_cast<uint32_t*>(
                Op + ((size_t)(beta * 1024 + gr)) * 1024 + hh * 64 + gc) =
                pack_bf2(v0, v1);
        } else {
            float* Yp = (float*)D0v;
            float2 xv = *reinterpret_cast<const float2*>(aux0 + (size_t)gr * 1024 + gc);
            float2 bv = *reinterpret_cast<const float2*>(aux1 + gc);
            *reinterpret_cast<float2*>(Yp + (size_t)gr * 1024 + gc) =
                make_float2(v0 + xv.x + bv.x, v1 + xv.y + bv.y);
        }
    };

#pragma unroll
    for (int mt = 0; mt < 2; mt++) {
#pragma unroll
        for (int nt = 0; nt < NT; nt++) {
            int gr0 = rowBase + wm * 32 + mt * 16 + group;
            int gc  = colBase + wn * WN + nt * 8 + tid4 * 2;
            emit(gr0,     gc, acc[mt][nt][0], acc[mt][nt][1]);
            emit(gr0 + 8, gc, acc[mt][nt][2], acc[mt][nt][3]);
        }
    }
}

// ---------------------------------------------------------------------------
// Column softmax stats (softmax over query axis i). Only valid i (>= j-1024).
// ---------------------------------------------------------------------------
__global__ __launch_bounds__(256) void colstats() {
    int bz = blockIdx.y;
    int j  = blockIdx.x * 256 + threadIdx.x;
    int i0 = j - 1024; if (i0 < 0) i0 = 0;
    const __nv_bfloat16* s = g_S + (size_t)bz * 1024 * 2048 + (size_t)i0 * 2048 + j;
    float m = -CUDART_INF_F;
    float z = 0.0f;
    for (int i = i0; i < 1024; i++, s += 2048) {
        float v = __bfloat162float(*s);
        float nm = fmaxf(m, v);
        z = z * fexp(m - nm) + fexp(v - nm);
        m = nm;
    }
    g_M [bz * 2048 + j] = m;
    g_RZ[bz * 2048 + j] = 1.0f / z;
}

// ---------------------------------------------------------------------------
__global__ __launch_bounds__(256) void ln_kernel(const float* __restrict__ gamma,
                                                 const float* __restrict__ beta,
                                                 float* __restrict__ out) {
    int row = blockIdx.x;
    const float4* yr = reinterpret_cast<const float4*>(g_y + (size_t)row * 1024);
    int t = threadIdx.x;
    float4 v = yr[t];
    float s  = v.x + v.y + v.z + v.w;
    float s2 = v.x * v.x + v.y * v.y + v.z * v.z + v.w * v.w;
#pragma unroll
    for (int off = 16; off; off >>= 1) {
        s  += __shfl_xor_sync(0xFFFFFFFFu, s,  off);
        s2 += __shfl_xor_sync(0xFFFFFFFFu, s2, off);
    }
    __shared__ float shs[8], shs2[8];
    int w = t >> 5, lane = t & 31;
    if (lane == 0) { shs[w] = s; shs2[w] = s2; }
    __syncthreads();
    float ts = 0.0f, ts2 = 0.0f;
#pragma unroll
    for (int i = 0; i < 8; i++) { ts += shs[i]; ts2 += shs2[i]; }
    float mu   = ts * (1.0f / 1024.0f);
    float var  = ts2 * (1.0f / 1024.0f) - mu * mu;
    float rstd = rsqrtf(var + 1e-5f);

    float4 g = reinterpret_cast<const float4*>(gamma)[t];
    float4 b = reinterpret_cast<const float4*>(beta)[t];
    float4 o;
    o.x = (v.x - mu) * rstd * g.x + b.x;
    o.y = (v.y - mu) * rstd * g.y + b.y;
    o.z = (v.z - mu) * rstd * g.z + b.z;
    o.w = (v.w - mu) * rstd * g.w + b.w;
    reinterpret_cast<float4*>(out + (size_t)row * 1024)[t] = o;
}

// ---------------------------------------------------------------------------
extern "C" void kernel_launch(void* const* d_in, const int* in_sizes, int n_in,
                              void* d_out, int out_size) {
    const float* x    = (const float*)d_in[0];
    const float* pos  = (const float*)d_in[1];
    const float* u    = (const float*)d_in[2];
    const float* v    = (const float*)d_in[3];
    const float* mem  = (const float*)d_in[4];
    const float* Wq   = (const float*)d_in[6];
    const float* Wkv  = (const float*)d_in[7];
    const float* Wfc  = (const float*)d_in[8];
    const float* bfc  = (const float*)d_in[9];
    const float* gam  = (const float*)d_in[10];
    const float* bet  = (const float*)d_in[11];
    float* out = (float*)d_out;

    __nv_bfloat16 *A2, *B2, *Vt, *h, *of, *Sp;
    float *y, *Mp, *Rp;
    cudaGetSymbolAddress((void**)&h,  g_h);
    cudaGetSymbolAddress((void**)&A2, g_A2);
    cudaGetSymbolAddress((void**)&B2, g_B2);
    cudaGetSymbolAddress((void**)&Vt, g_V);
    cudaGetSymbolAddress((void**)&of, g_of);
    cudaGetSymbolAddress((void**)&y,  g_y);
    cudaGetSymbolAddress((void**)&Sp, g_S);
    cudaGetSymbolAddress((void**)&Mp, g_M);
    cudaGetSymbolAddress((void**)&Rp, g_RZ);

    concat_h  <<<4096, 256>>>(x, mem);
    fill_pos  <<<4096, 256>>>(pos);
    zero_a2row<<<4, 256>>>();

    // G0: q = x@Wq^T -> A2 (q+u | shifted q+v)
    gemm_bf16<0, 64><<<dim3(16, 16, 1), 256>>>(x, Wq, 1024, 0, 0, u, v, A2, nullptr);
    // G1: kv = h@Wkv^T -> B2 k-half + Vt
    gemm_bf16<1, 128><<<dim3(16, 32, 1), 256>>>(h, Wkv, 1024, 0, 0, nullptr, nullptr, B2, Vt);
    // G2: S = A2@B2^T batched over 32, K=128, mask+scale
    gemm_bf16<2, 128><<<dim3(16, 8, 32), 256>>>(A2, B2, 128,
        (size_t)1024 * 128, (size_t)2048 * 128, nullptr, nullptr, Sp, nullptr);
    // softmax stats over query axis
    colstats<<<dim3(8, 32), 256>>>();
    // G3: out = (exp(S - M) * RZ) @ Vt^T
    gemm_bf16<3, 64><<<dim3(1, 8, 32), 256>>>(Sp, Vt, 2048,
        (size_t)1024 * 2048, (size_t)64 * 2048, Mp, Rp, of, nullptr);
    // G4: y = of@Wfc^T + x + bfc
    gemm_bf16<4, 64><<<dim3(16, 16, 1), 256>>>(of, Wfc, 1024, 0, 0, x, bfc, y, nullptr);
    // LayerNorm
    ln_kernel<<<2048, 256>>>(gam, bet, out);
}